// round 6
// baseline (speedup 1.0000x reference)
#include <cuda_runtime.h>

#define NN 100000
#define EE 3200000
#define GG 512
#define INC 128

// ---------------- scratch (static device globals; no allocation) -------------
__device__ int   g_deg[NN];
__device__ int   g_rowptr[NN + 1];
__device__ int   g_cursor[NN];
__device__ int   g_bsums[1024];
__device__ int   g_boffs[1024];
__device__ int   g_col[EE];
__device__ float g_h1[NN * 64];
__device__ float g_as1[NN * 8];
__device__ float g_ad1[NN * 8];
__device__ float g_out1[NN * 64];
__device__ float g_h2[NN * 64];
__device__ float g_as2[NN];
__device__ float g_ad2[NN];
__device__ float g_pool[GG * 64];
__device__ int   g_gcnt[GG];

// ---------------- CSR build --------------------------------------------------
__global__ void k_zero() {
    int i = blockIdx.x * blockDim.x + threadIdx.x;
    if (i < NN) g_deg[i] = 0;
    if (i < GG * 64) g_pool[i] = 0.f;
    if (i < GG) g_gcnt[i] = 0;
}

__global__ void k_count(const int4* __restrict__ dst4) {
    int i = blockIdx.x * blockDim.x + threadIdx.x;
    if (i < EE / 4) {
        int4 d = dst4[i];
        atomicAdd(&g_deg[d.x], 1);
        atomicAdd(&g_deg[d.y], 1);
        atomicAdd(&g_deg[d.z], 1);
        atomicAdd(&g_deg[d.w], 1);
    }
}

__global__ void k_scan1() {
    __shared__ int sh[1024];
    int t = threadIdx.x;
    int i = blockIdx.x * 1024 + t;
    int v = (i < NN) ? g_deg[i] : 0;
    sh[t] = v; __syncthreads();
    for (int off = 1; off < 1024; off <<= 1) {
        int tv = (t >= off) ? sh[t - off] : 0;
        __syncthreads();
        sh[t] += tv;
        __syncthreads();
    }
    if (i < NN) g_rowptr[i] = sh[t] - v;     // exclusive
    if (t == 1023) g_bsums[blockIdx.x] = sh[1023];
}

__global__ void k_scan2(int nb) {
    __shared__ int sh[1024];
    int t = threadIdx.x;
    int v = (t < nb) ? g_bsums[t] : 0;
    sh[t] = v; __syncthreads();
    for (int off = 1; off < 1024; off <<= 1) {
        int tv = (t >= off) ? sh[t - off] : 0;
        __syncthreads();
        sh[t] += tv;
        __syncthreads();
    }
    g_boffs[t] = sh[t] - v;
    if (t == 1023) g_rowptr[NN] = sh[1023];  // == EE
}

__global__ void k_scan3() {
    int i = blockIdx.x * 1024 + threadIdx.x;
    if (i < NN) {
        int v = g_rowptr[i] + g_boffs[blockIdx.x];
        g_rowptr[i] = v;
        g_cursor[i] = v;
    }
}

__global__ void k_fill(const int4* __restrict__ src4, const int4* __restrict__ dst4) {
    int i = blockIdx.x * blockDim.x + threadIdx.x;
    if (i < EE / 4) {
        int4 s = src4[i];
        int4 d = dst4[i];
        g_col[atomicAdd(&g_cursor[d.x], 1)] = s.x;
        g_col[atomicAdd(&g_cursor[d.y], 1)] = s.y;
        g_col[atomicAdd(&g_cursor[d.z], 1)] = s.z;
        g_col[atomicAdd(&g_cursor[d.w], 1)] = s.w;
    }
}

// ---------------- GEMM (x[N,K] @ W[K,64]) -----------------------------------
template <int K>
__device__ __forceinline__ void gemm_body(const float* __restrict__ x,
                                          const float* __restrict__ W,
                                          float* __restrict__ out) {
    __shared__ float ws[K * 64];
    __shared__ float xs[32 * K];
    int t = threadIdx.x;
    int row0 = blockIdx.x * 32;
    for (int i = t; i < K * 64; i += 256) ws[i] = W[i];
    for (int i = t; i < 32 * K; i += 256) {
        int r = i / K, c = i - r * K;
        xs[i] = x[(row0 + r) * K + c];     // NN % 32 == 0, no guard needed
    }
    __syncthreads();
    int cg = (t & 15) * 4;
    int r0 = (t >> 4) * 2;
    float4 a0 = make_float4(0.f, 0.f, 0.f, 0.f);
    float4 a1 = make_float4(0.f, 0.f, 0.f, 0.f);
    #pragma unroll 8
    for (int k = 0; k < K; k++) {
        float4 w = *(const float4*)&ws[k * 64 + cg];
        float x0 = xs[r0 * K + k];
        float x1 = xs[(r0 + 1) * K + k];
        a0.x += x0 * w.x; a0.y += x0 * w.y; a0.z += x0 * w.z; a0.w += x0 * w.w;
        a1.x += x1 * w.x; a1.y += x1 * w.y; a1.z += x1 * w.z; a1.w += x1 * w.w;
    }
    int gr = row0 + r0;
    *(float4*)&out[gr * 64 + cg] = a0;
    *(float4*)&out[(gr + 1) * 64 + cg] = a1;
}

__global__ void k_gemm1(const float* __restrict__ x, const float* __restrict__ W) {
    gemm_body<128>(x, W, g_h1);
}
__global__ void k_gemm2(const float* __restrict__ W) {
    gemm_body<64>(g_out1, W, g_h2);
}

// ---------------- attention coefficients ------------------------------------
__global__ void k_att1(const float* __restrict__ asrc, const float* __restrict__ adst) {
    int idx = blockIdx.x * blockDim.x + threadIdx.x;
    if (idx >= NN * 8) return;
    int n = idx >> 3, h = idx & 7;
    const float* hp = &g_h1[n * 64 + h * 8];
    float s = 0.f, d = 0.f;
    #pragma unroll
    for (int c = 0; c < 8; c++) {
        float v = hp[c];
        s += v * asrc[h * 8 + c];
        d += v * adst[h * 8 + c];
    }
    g_as1[idx] = s;
    g_ad1[idx] = d;
}

__global__ void k_att2(const float* __restrict__ asrc, const float* __restrict__ adst) {
    int gt = blockIdx.x * blockDim.x + threadIdx.x;
    int node = gt >> 5;
    if (node >= NN) return;
    int lane = gt & 31;
    float2 v = ((const float2*)(g_h2 + node * 64))[lane];
    float2 a = ((const float2*)asrc)[lane];
    float2 b = ((const float2*)adst)[lane];
    float s = v.x * a.x + v.y * a.y;
    float d = v.x * b.x + v.y * b.y;
    #pragma unroll
    for (int off = 16; off; off >>= 1) {
        s += __shfl_down_sync(0xffffffffu, s, off);
        d += __shfl_down_sync(0xffffffffu, d, off);
    }
    if (lane == 0) { g_as2[node] = s; g_ad2[node] = d; }
}

// ---------------- GAT aggregation (warp per dst node) ------------------------
// Branchless softmax without running max (shift-invariant; |e| is small here).
// Uniform int4 loads of g_col (4 edges per LDG.128 broadcast), unroll x8 with
// all 16 gathers issued before any use -> ~24 loads in flight per warp.

#define LEAKY(v) ((v) > 0.f ? (v) : 0.2f * (v))

#define AGG1_EDGE(SRC, EVAR, XVAR)                            \
    float EVAR = __ldg(&g_as1[(SRC) * 8 + head]);             \
    float2 XVAR = __ldg(&H[(SRC) * 32 + lane]);

__global__ void __launch_bounds__(256) k_agg1(const float* __restrict__ b1) {
    int gt = blockIdx.x * blockDim.x + threadIdx.x;
    int node = gt >> 5;
    if (node >= NN) return;
    int lane = gt & 31;
    int head = lane >> 2;
    float adv = g_ad1[node * 8 + head];
    float e = g_as1[node * 8 + head] + adv;     // self loop
    float p = __expf(LEAKY(e));
    const float2* __restrict__ H = (const float2*)g_h1;
    float2 hv = __ldg(&H[node * 32 + lane]);
    float s = p, a0 = hv.x * p, a1 = hv.y * p;
    int i = g_rowptr[node], en = g_rowptr[node + 1];
    // lead-in to 16B-aligned index
    for (; i < en && (i & 3); i++) {
        int src = g_col[i];
        float ev = __ldg(&g_as1[src * 8 + head]) + adv;
        float pp = __expf(LEAKY(ev));
        float2 xv = __ldg(&H[src * 32 + lane]);
        s += pp; a0 += xv.x * pp; a1 += xv.y * pp;
    }
    for (; i + 8 <= en; i += 8) {
        int4 c0 = *(const int4*)&g_col[i];
        int4 c1 = *(const int4*)&g_col[i + 4];
        AGG1_EDGE(c0.x, e0, x0) AGG1_EDGE(c0.y, e1, x1)
        AGG1_EDGE(c0.z, e2, x2) AGG1_EDGE(c0.w, e3, x3)
        AGG1_EDGE(c1.x, e4, x4) AGG1_EDGE(c1.y, e5, x5)
        AGG1_EDGE(c1.z, e6, x6) AGG1_EDGE(c1.w, e7, x7)
        float p0 = __expf(LEAKY(e0 + adv));
        float p1 = __expf(LEAKY(e1 + adv));
        float p2 = __expf(LEAKY(e2 + adv));
        float p3 = __expf(LEAKY(e3 + adv));
        float p4 = __expf(LEAKY(e4 + adv));
        float p5 = __expf(LEAKY(e5 + adv));
        float p6 = __expf(LEAKY(e6 + adv));
        float p7 = __expf(LEAKY(e7 + adv));
        s  += ((p0 + p1) + (p2 + p3)) + ((p4 + p5) + (p6 + p7));
        a0 += x0.x * p0 + x1.x * p1 + x2.x * p2 + x3.x * p3
            + x4.x * p4 + x5.x * p5 + x6.x * p6 + x7.x * p7;
        a1 += x0.y * p0 + x1.y * p1 + x2.y * p2 + x3.y * p3
            + x4.y * p4 + x5.y * p5 + x6.y * p6 + x7.y * p7;
    }
    if (i + 4 <= en) {
        int4 c0 = *(const int4*)&g_col[i];
        AGG1_EDGE(c0.x, e0, x0) AGG1_EDGE(c0.y, e1, x1)
        AGG1_EDGE(c0.z, e2, x2) AGG1_EDGE(c0.w, e3, x3)
        float p0 = __expf(LEAKY(e0 + adv));
        float p1 = __expf(LEAKY(e1 + adv));
        float p2 = __expf(LEAKY(e2 + adv));
        float p3 = __expf(LEAKY(e3 + adv));
        s  += (p0 + p1) + (p2 + p3);
        a0 += x0.x * p0 + x1.x * p1 + x2.x * p2 + x3.x * p3;
        a1 += x0.y * p0 + x1.y * p1 + x2.y * p2 + x3.y * p3;
        i += 4;
    }
    for (; i < en; i++) {
        int src = g_col[i];
        float ev = __ldg(&g_as1[src * 8 + head]) + adv;
        float pp = __expf(LEAKY(ev));
        float2 xv = __ldg(&H[src * 32 + lane]);
        s += pp; a0 += xv.x * pp; a1 += xv.y * pp;
    }
    float inv = 1.f / fmaxf(s, 1e-16f);
    float v0 = a0 * inv + b1[lane * 2];
    float v1 = a1 * inv + b1[lane * 2 + 1];
    v0 = v0 > 0.f ? v0 : (__expf(v0) - 1.f);   // ELU
    v1 = v1 > 0.f ? v1 : (__expf(v1) - 1.f);
    ((float2*)(g_out1 + node * 64))[lane] = make_float2(v0, v1);
}

#define AGG2_EDGE(SRC, EVAR, XVAR)                 \
    float EVAR = __ldg(&g_as2[(SRC)]);             \
    float2 XVAR = __ldg(&H[(SRC) * 32 + lane]);

// agg2 + global_mean_pool (sum part) fused.
__global__ void __launch_bounds__(256) k_agg2(const float* __restrict__ b2,
                                              const int* __restrict__ batch) {
    int gt = blockIdx.x * blockDim.x + threadIdx.x;
    int node = gt >> 5;
    if (node >= NN) return;
    int lane = gt & 31;
    float adv = g_ad2[node];
    float e = g_as2[node] + adv;
    float p = __expf(LEAKY(e));
    const float2* __restrict__ H = (const float2*)g_h2;
    float2 hv = __ldg(&H[node * 32 + lane]);
    float s = p, a0 = hv.x * p, a1 = hv.y * p;
    int i = g_rowptr[node], en = g_rowptr[node + 1];
    for (; i < en && (i & 3); i++) {
        int src = g_col[i];
        float ev = __ldg(&g_as2[src]) + adv;
        float pp = __expf(LEAKY(ev));
        float2 xv = __ldg(&H[src * 32 + lane]);
        s += pp; a0 += xv.x * pp; a1 += xv.y * pp;
    }
    for (; i + 8 <= en; i += 8) {
        int4 c0 = *(const int4*)&g_col[i];
        int4 c1 = *(const int4*)&g_col[i + 4];
        AGG2_EDGE(c0.x, e0, x0) AGG2_EDGE(c0.y, e1, x1)
        AGG2_EDGE(c0.z, e2, x2) AGG2_EDGE(c0.w, e3, x3)
        AGG2_EDGE(c1.x, e4, x4) AGG2_EDGE(c1.y, e5, x5)
        AGG2_EDGE(c1.z, e6, x6) AGG2_EDGE(c1.w, e7, x7)
        float p0 = __expf(LEAKY(e0 + adv));
        float p1 = __expf(LEAKY(e1 + adv));
        float p2 = __expf(LEAKY(e2 + adv));
        float p3 = __expf(LEAKY(e3 + adv));
        float p4 = __expf(LEAKY(e4 + adv));
        float p5 = __expf(LEAKY(e5 + adv));
        float p6 = __expf(LEAKY(e6 + adv));
        float p7 = __expf(LEAKY(e7 + adv));
        s  += ((p0 + p1) + (p2 + p3)) + ((p4 + p5) + (p6 + p7));
        a0 += x0.x * p0 + x1.x * p1 + x2.x * p2 + x3.x * p3
            + x4.x * p4 + x5.x * p5 + x6.x * p6 + x7.x * p7;
        a1 += x0.y * p0 + x1.y * p1 + x2.y * p2 + x3.y * p3
            + x4.y * p4 + x5.y * p5 + x6.y * p6 + x7.y * p7;
    }
    if (i + 4 <= en) {
        int4 c0 = *(const int4*)&g_col[i];
        AGG2_EDGE(c0.x, e0, x0) AGG2_EDGE(c0.y, e1, x1)
        AGG2_EDGE(c0.z, e2, x2) AGG2_EDGE(c0.w, e3, x3)
        float p0 = __expf(LEAKY(e0 + adv));
        float p1 = __expf(LEAKY(e1 + adv));
        float p2 = __expf(LEAKY(e2 + adv));
        float p3 = __expf(LEAKY(e3 + adv));
        s  += (p0 + p1) + (p2 + p3);
        a0 += x0.x * p0 + x1.x * p1 + x2.x * p2 + x3.x * p3;
        a1 += x0.y * p0 + x1.y * p1 + x2.y * p2 + x3.y * p3;
        i += 4;
    }
    for (; i < en; i++) {
        int src = g_col[i];
        float ev = __ldg(&g_as2[src]) + adv;
        float pp = __expf(LEAKY(ev));
        float2 xv = __ldg(&H[src * 32 + lane]);
        s += pp; a0 += xv.x * pp; a1 += xv.y * pp;
    }
    float inv = 1.f / fmaxf(s, 1e-16f);
    float v0 = a0 * inv + b2[lane * 2];
    float v1 = a1 * inv + b2[lane * 2 + 1];
    int b = batch[node];
    atomicAdd(&g_pool[b * 64 + lane * 2], v0);       // RED (no return)
    atomicAdd(&g_pool[b * 64 + lane * 2 + 1], v1);
    if (lane == 0) atomicAdd(&g_gcnt[b], 1);
}

// ---------------- MLP head ----------------------------------------------------
__global__ void k_mlp(const float* __restrict__ lw1, const float* __restrict__ lb1,
                      const float* __restrict__ lw2, const float* __restrict__ lb2,
                      float* __restrict__ out) {
    int g = blockIdx.x;
    int t = threadIdx.x;   // 128
    __shared__ float gm[64];
    __shared__ float red[128];
    if (t < 64) {
        float c = (float)max(g_gcnt[g], 1);
        gm[t] = g_pool[g * 64 + t] / c;
    }
    __syncthreads();
    float acc = lb1[t];
    #pragma unroll 8
    for (int k = 0; k < 64; k++) acc += gm[k] * lw1[k * 128 + t];
    float hv = acc > 0.f ? acc : (__expf(acc) - 1.f);   // ELU
    red[t] = hv * lw2[t];
    __syncthreads();
    for (int sft = 64; sft > 0; sft >>= 1) {
        if (t < sft) red[t] += red[t + sft];
        __syncthreads();
    }
    if (t == 0) out[g] = red[0] + lb2[0];
}

// ---------------- launch ------------------------------------------------------
extern "C" void kernel_launch(void* const* d_in, const int* in_sizes, int n_in,
                              void* d_out, int out_size) {
    int iEI, iBatch, iW1, iAS1, iAD1, iB1, iW2, iAS2, iAD2, iB2, iLW1, iLB1, iLW2, iLB2;
    if (in_sizes[1] == 2 * EE) {
        iEI = 1; iBatch = 2; iW1 = 3; iAS1 = 4; iAD1 = 5; iB1 = 6;
        iW2 = 7; iAS2 = 8; iAD2 = 9; iB2 = 10; iLW1 = 11; iLB1 = 12; iLW2 = 13; iLB2 = 14;
    } else {
        iW1 = 1; iAS1 = 2; iAD1 = 3; iB1 = 4; iW2 = 5; iAS2 = 6; iAD2 = 7; iB2 = 8;
        iLW1 = 9; iLB1 = 10; iLW2 = 11; iLB2 = 12; iEI = 13; iBatch = 14;
    }
    const float* x     = (const float*)d_in[0];
    const int*   ei    = (const int*)d_in[iEI];
    const int*   batch = (const int*)d_in[iBatch];
    const float* W1    = (const float*)d_in[iW1];
    const float* AS1   = (const float*)d_in[iAS1];
    const float* AD1   = (const float*)d_in[iAD1];
    const float* B1    = (const float*)d_in[iB1];
    const float* W2    = (const float*)d_in[iW2];
    const float* AS2   = (const float*)d_in[iAS2];
    const float* AD2   = (const float*)d_in[iAD2];
    const float* B2    = (const float*)d_in[iB2];
    const float* LW1   = (const float*)d_in[iLW1];
    const float* LB1   = (const float*)d_in[iLB1];
    const float* LW2   = (const float*)d_in[iLW2];
    const float* LB2   = (const float*)d_in[iLB2];
    float* out = (float*)d_out;

    const int4* esrc4 = (const int4*)ei;
    const int4* edst4 = (const int4*)(ei + EE);

    int nb = (NN + 1023) / 1024;

    k_zero<<<(NN + 255) / 256, 256>>>();
    k_count<<<(EE / 4 + 255) / 256, 256>>>(edst4);
    k_scan1<<<nb, 1024>>>();
    k_scan2<<<1, 1024>>>(nb);
    k_scan3<<<nb, 1024>>>();
    k_fill<<<(EE / 4 + 255) / 256, 256>>>(esrc4, edst4);

    k_gemm1<<<NN / 32, 256>>>(x, W1);
    k_att1<<<(NN * 8 + 255) / 256, 256>>>(AS1, AD1);
    k_agg1<<<(NN * 32 + 255) / 256, 256>>>(B1);

    k_gemm2<<<NN / 32, 256>>>(W2);
    k_att2<<<(NN * 32 + 255) / 256, 256>>>(AS2, AD2);
    k_agg2<<<(NN * 32 + 255) / 256, 256>>>(B2, batch);

    k_mlp<<<GG, 128>>>(LW1, LB1, LW2, LB2, out);
}

// round 7
// speedup vs baseline: 1.0608x; 1.0608x over previous
#include <cuda_runtime.h>

#define NN 100000
#define EE 3200000
#define GG 512
#define INC 128

// ---------------- scratch (static device globals; no allocation) -------------
__device__ int   g_deg[NN];
__device__ int   g_rowptr[NN + 1];
__device__ int   g_cursor[NN];
__device__ int   g_bsums[1024];
__device__ int   g_boffs[1024];
__device__ int   g_col[EE];
__device__ float g_h1[NN * 64];
__device__ float g_as1[NN * 8];
__device__ float g_ad1[NN * 8];
__device__ float g_out1[NN * 64];
__device__ float g_h2[NN * 64];
__device__ float g_as2[NN];
__device__ float g_ad2[NN];
__device__ float g_pool[GG * 64];
__device__ int   g_gcnt[GG];

// ---------------- CSR build --------------------------------------------------
__global__ void k_zero() {
    int i = blockIdx.x * blockDim.x + threadIdx.x;
    if (i < NN) g_deg[i] = 0;
    if (i < GG * 64) g_pool[i] = 0.f;
    if (i < GG) g_gcnt[i] = 0;
}

__global__ void k_count(const int4* __restrict__ dst4) {
    int i = blockIdx.x * blockDim.x + threadIdx.x;
    if (i < EE / 4) {
        int4 d = dst4[i];
        atomicAdd(&g_deg[d.x], 1);
        atomicAdd(&g_deg[d.y], 1);
        atomicAdd(&g_deg[d.z], 1);
        atomicAdd(&g_deg[d.w], 1);
    }
}

__global__ void k_scan1() {
    __shared__ int sh[1024];
    int t = threadIdx.x;
    int i = blockIdx.x * 1024 + t;
    int v = (i < NN) ? g_deg[i] : 0;
    sh[t] = v; __syncthreads();
    for (int off = 1; off < 1024; off <<= 1) {
        int tv = (t >= off) ? sh[t - off] : 0;
        __syncthreads();
        sh[t] += tv;
        __syncthreads();
    }
    if (i < NN) g_rowptr[i] = sh[t] - v;     // exclusive
    if (t == 1023) g_bsums[blockIdx.x] = sh[1023];
}

__global__ void k_scan2(int nb) {
    __shared__ int sh[1024];
    int t = threadIdx.x;
    int v = (t < nb) ? g_bsums[t] : 0;
    sh[t] = v; __syncthreads();
    for (int off = 1; off < 1024; off <<= 1) {
        int tv = (t >= off) ? sh[t - off] : 0;
        __syncthreads();
        sh[t] += tv;
        __syncthreads();
    }
    g_boffs[t] = sh[t] - v;
    if (t == 1023) g_rowptr[NN] = sh[1023];  // == EE
}

__global__ void k_scan3() {
    int i = blockIdx.x * 1024 + threadIdx.x;
    if (i < NN) {
        int v = g_rowptr[i] + g_boffs[blockIdx.x];
        g_rowptr[i] = v;
        g_cursor[i] = v;
    }
}

__global__ void k_fill(const int4* __restrict__ src4, const int4* __restrict__ dst4) {
    int i = blockIdx.x * blockDim.x + threadIdx.x;
    if (i < EE / 4) {
        int4 s = src4[i];
        int4 d = dst4[i];
        g_col[atomicAdd(&g_cursor[d.x], 1)] = s.x;
        g_col[atomicAdd(&g_cursor[d.y], 1)] = s.y;
        g_col[atomicAdd(&g_cursor[d.z], 1)] = s.z;
        g_col[atomicAdd(&g_cursor[d.w], 1)] = s.w;
    }
}

// ---------------- GEMM (x[N,K] @ W[K,64]) -----------------------------------
template <int K>
__device__ __forceinline__ void gemm_body(const float* __restrict__ x,
                                          const float* __restrict__ W,
                                          float* __restrict__ out) {
    __shared__ float ws[K * 64];
    __shared__ float xs[32 * K];
    int t = threadIdx.x;
    int row0 = blockIdx.x * 32;
    for (int i = t; i < K * 64; i += 256) ws[i] = W[i];
    for (int i = t; i < 32 * K; i += 256) {
        int r = i / K, c = i - r * K;
        xs[i] = x[(row0 + r) * K + c];     // NN % 32 == 0, no guard needed
    }
    __syncthreads();
    int cg = (t & 15) * 4;
    int r0 = (t >> 4) * 2;
    float4 a0 = make_float4(0.f, 0.f, 0.f, 0.f);
    float4 a1 = make_float4(0.f, 0.f, 0.f, 0.f);
    #pragma unroll 8
    for (int k = 0; k < K; k++) {
        float4 w = *(const float4*)&ws[k * 64 + cg];
        float x0 = xs[r0 * K + k];
        float x1 = xs[(r0 + 1) * K + k];
        a0.x += x0 * w.x; a0.y += x0 * w.y; a0.z += x0 * w.z; a0.w += x0 * w.w;
        a1.x += x1 * w.x; a1.y += x1 * w.y; a1.z += x1 * w.z; a1.w += x1 * w.w;
    }
    int gr = row0 + r0;
    *(float4*)&out[gr * 64 + cg] = a0;
    *(float4*)&out[(gr + 1) * 64 + cg] = a1;
}

__global__ void k_gemm1(const float* __restrict__ x, const float* __restrict__ W) {
    gemm_body<128>(x, W, g_h1);
}
__global__ void k_gemm2(const float* __restrict__ W) {
    gemm_body<64>(g_out1, W, g_h2);
}

// ---------------- attention coefficients ------------------------------------
__global__ void k_att1(const float* __restrict__ asrc, const float* __restrict__ adst) {
    int idx = blockIdx.x * blockDim.x + threadIdx.x;
    if (idx >= NN * 8) return;
    int n = idx >> 3, h = idx & 7;
    const float* hp = &g_h1[n * 64 + h * 8];
    float s = 0.f, d = 0.f;
    #pragma unroll
    for (int c = 0; c < 8; c++) {
        float v = hp[c];
        s += v * asrc[h * 8 + c];
        d += v * adst[h * 8 + c];
    }
    g_as1[idx] = s;
    g_ad1[idx] = d;
}

__global__ void k_att2(const float* __restrict__ asrc, const float* __restrict__ adst) {
    int gt = blockIdx.x * blockDim.x + threadIdx.x;
    int node = gt >> 5;
    if (node >= NN) return;
    int lane = gt & 31;
    float2 v = ((const float2*)(g_h2 + node * 64))[lane];
    float2 a = ((const float2*)asrc)[lane];
    float2 b = ((const float2*)adst)[lane];
    float s = v.x * a.x + v.y * a.y;
    float d = v.x * b.x + v.y * b.y;
    #pragma unroll
    for (int off = 16; off; off >>= 1) {
        s += __shfl_down_sync(0xffffffffu, s, off);
        d += __shfl_down_sync(0xffffffffu, d, off);
    }
    if (lane == 0) { g_as2[node] = s; g_ad2[node] = d; }
}

// ---------------- GAT aggregation (warp per dst node) ------------------------
// Branchless softmax without running max (shift-invariant; |e| is small here).
// Serial uniform loop over CSR row, manually unrolled x4 with all gathers
// issued before any use -> explicit MLP to hide L2 latency.

#define LEAKY(v) ((v) > 0.f ? (v) : 0.2f * (v))

__global__ void __launch_bounds__(256) k_agg1(const float* __restrict__ b1) {
    int gt = blockIdx.x * blockDim.x + threadIdx.x;
    int node = gt >> 5;
    if (node >= NN) return;
    int lane = gt & 31;
    int head = lane >> 2;
    float adv = g_ad1[node * 8 + head];
    float e = g_as1[node * 8 + head] + adv;     // self loop
    float p = __expf(LEAKY(e));
    const float2* __restrict__ H = (const float2*)g_h1;
    float2 hv = __ldg(&H[node * 32 + lane]);
    float s = p, a0 = hv.x * p, a1 = hv.y * p;
    int i = g_rowptr[node], en = g_rowptr[node + 1];
    for (; i + 4 <= en; i += 4) {
        int s0 = g_col[i],     s1 = g_col[i + 1];
        int s2 = g_col[i + 2], s3 = g_col[i + 3];
        float e0 = __ldg(&g_as1[s0 * 8 + head]);
        float e1 = __ldg(&g_as1[s1 * 8 + head]);
        float e2 = __ldg(&g_as1[s2 * 8 + head]);
        float e3 = __ldg(&g_as1[s3 * 8 + head]);
        float2 x0 = __ldg(&H[s0 * 32 + lane]);
        float2 x1 = __ldg(&H[s1 * 32 + lane]);
        float2 x2 = __ldg(&H[s2 * 32 + lane]);
        float2 x3 = __ldg(&H[s3 * 32 + lane]);
        float p0 = __expf(LEAKY(e0 + adv));
        float p1 = __expf(LEAKY(e1 + adv));
        float p2 = __expf(LEAKY(e2 + adv));
        float p3 = __expf(LEAKY(e3 + adv));
        s  += (p0 + p1) + (p2 + p3);
        a0 += x0.x * p0 + x1.x * p1 + x2.x * p2 + x3.x * p3;
        a1 += x0.y * p0 + x1.y * p1 + x2.y * p2 + x3.y * p3;
    }
    for (; i < en; i++) {
        int src = g_col[i];
        float ev = __ldg(&g_as1[src * 8 + head]) + adv;
        float pp = __expf(LEAKY(ev));
        float2 xv = __ldg(&H[src * 32 + lane]);
        s += pp; a0 += xv.x * pp; a1 += xv.y * pp;
    }
    float inv = 1.f / fmaxf(s, 1e-16f);
    float v0 = a0 * inv + b1[lane * 2];
    float v1 = a1 * inv + b1[lane * 2 + 1];
    v0 = v0 > 0.f ? v0 : (__expf(v0) - 1.f);   // ELU
    v1 = v1 > 0.f ? v1 : (__expf(v1) - 1.f);
    ((float2*)(g_out1 + node * 64))[lane] = make_float2(v0, v1);
}

// agg2 + global_mean_pool (sum part) fused.
__global__ void __launch_bounds__(256) k_agg2(const float* __restrict__ b2,
                                              const int* __restrict__ batch) {
    int gt = blockIdx.x * blockDim.x + threadIdx.x;
    int node = gt >> 5;
    if (node >= NN) return;
    int lane = gt & 31;
    float adv = g_ad2[node];
    float e = g_as2[node] + adv;
    float p = __expf(LEAKY(e));
    const float2* __restrict__ H = (const float2*)g_h2;
    float2 hv = __ldg(&H[node * 32 + lane]);
    float s = p, a0 = hv.x * p, a1 = hv.y * p;
    int i = g_rowptr[node], en = g_rowptr[node + 1];
    for (; i + 4 <= en; i += 4) {
        int s0 = g_col[i],     s1 = g_col[i + 1];
        int s2 = g_col[i + 2], s3 = g_col[i + 3];
        float e0 = __ldg(&g_as2[s0]);
        float e1 = __ldg(&g_as2[s1]);
        float e2 = __ldg(&g_as2[s2]);
        float e3 = __ldg(&g_as2[s3]);
        float2 x0 = __ldg(&H[s0 * 32 + lane]);
        float2 x1 = __ldg(&H[s1 * 32 + lane]);
        float2 x2 = __ldg(&H[s2 * 32 + lane]);
        float2 x3 = __ldg(&H[s3 * 32 + lane]);
        float p0 = __expf(LEAKY(e0 + adv));
        float p1 = __expf(LEAKY(e1 + adv));
        float p2 = __expf(LEAKY(e2 + adv));
        float p3 = __expf(LEAKY(e3 + adv));
        s  += (p0 + p1) + (p2 + p3);
        a0 += x0.x * p0 + x1.x * p1 + x2.x * p2 + x3.x * p3;
        a1 += x0.y * p0 + x1.y * p1 + x2.y * p2 + x3.y * p3;
    }
    for (; i < en; i++) {
        int src = g_col[i];
        float ev = __ldg(&g_as2[src]) + adv;
        float pp = __expf(LEAKY(ev));
        float2 xv = __ldg(&H[src * 32 + lane]);
        s += pp; a0 += xv.x * pp; a1 += xv.y * pp;
    }
    float inv = 1.f / fmaxf(s, 1e-16f);
    float v0 = a0 * inv + b2[lane * 2];
    float v1 = a1 * inv + b2[lane * 2 + 1];
    int b = batch[node];
    atomicAdd(&g_pool[b * 64 + lane * 2], v0);       // RED (no return)
    atomicAdd(&g_pool[b * 64 + lane * 2 + 1], v1);
    if (lane == 0) atomicAdd(&g_gcnt[b], 1);
}

// ---------------- MLP head ----------------------------------------------------
__global__ void k_mlp(const float* __restrict__ lw1, const float* __restrict__ lb1,
                      const float* __restrict__ lw2, const float* __restrict__ lb2,
                      float* __restrict__ out) {
    int g = blockIdx.x;
    int t = threadIdx.x;   // 128
    __shared__ float gm[64];
    __shared__ float red[128];
    if (t < 64) {
        float c = (float)max(g_gcnt[g], 1);
        gm[t] = g_pool[g * 64 + t] / c;
    }
    __syncthreads();
    float acc = lb1[t];
    #pragma unroll 8
    for (int k = 0; k < 64; k++) acc += gm[k] * lw1[k * 128 + t];
    float hv = acc > 0.f ? acc : (__expf(acc) - 1.f);   // ELU
    red[t] = hv * lw2[t];
    __syncthreads();
    for (int sft = 64; sft > 0; sft >>= 1) {
        if (t < sft) red[t] += red[t + sft];
        __syncthreads();
    }
    if (t == 0) out[g] = red[0] + lb2[0];
}

// ---------------- launch ------------------------------------------------------
extern "C" void kernel_launch(void* const* d_in, const int* in_sizes, int n_in,
                              void* d_out, int out_size) {
    int iEI, iBatch, iW1, iAS1, iAD1, iB1, iW2, iAS2, iAD2, iB2, iLW1, iLB1, iLW2, iLB2;
    if (in_sizes[1] == 2 * EE) {
        iEI = 1; iBatch = 2; iW1 = 3; iAS1 = 4; iAD1 = 5; iB1 = 6;
        iW2 = 7; iAS2 = 8; iAD2 = 9; iB2 = 10; iLW1 = 11; iLB1 = 12; iLW2 = 13; iLB2 = 14;
    } else {
        iW1 = 1; iAS1 = 2; iAD1 = 3; iB1 = 4; iW2 = 5; iAS2 = 6; iAD2 = 7; iB2 = 8;
        iLW1 = 9; iLB1 = 10; iLW2 = 11; iLB2 = 12; iEI = 13; iBatch = 14;
    }
    const float* x     = (const float*)d_in[0];
    const int*   ei    = (const int*)d_in[iEI];
    const int*   batch = (const int*)d_in[iBatch];
    const float* W1    = (const float*)d_in[iW1];
    const float* AS1   = (const float*)d_in[iAS1];
    const float* AD1   = (const float*)d_in[iAD1];
    const float* B1    = (const float*)d_in[iB1];
    const float* W2    = (const float*)d_in[iW2];
    const float* AS2   = (const float*)d_in[iAS2];
    const float* AD2   = (const float*)d_in[iAD2];
    const float* B2    = (const float*)d_in[iB2];
    const float* LW1   = (const float*)d_in[iLW1];
    const float* LB1   = (const float*)d_in[iLB1];
    const float* LW2   = (const float*)d_in[iLW2];
    const float* LB2   = (const float*)d_in[iLB2];
    float* out = (float*)d_out;

    const int4* esrc4 = (const int4*)ei;
    const int4* edst4 = (const int4*)(ei + EE);

    int nb = (NN + 1023) / 1024;

    // Side stream + events for fork/join (created once, on the non-captured
    // correctness call; reused verbatim on the capture call).
    static cudaStream_t s1 = nullptr;
    static cudaEvent_t evFork = nullptr, evJoin = nullptr;
    if (!s1) {
        cudaStreamCreateWithFlags(&s1, cudaStreamNonBlocking);
        cudaEventCreateWithFlags(&evFork, cudaEventDisableTiming);
        cudaEventCreateWithFlags(&evJoin, cudaEventDisableTiming);
    }

    // Fork: side stream runs layer-1 GEMM + att concurrently with CSR build.
    cudaEventRecord(evFork, 0);
    cudaStreamWaitEvent(s1, evFork, 0);
    k_gemm1<<<NN / 32, 256, 0, s1>>>(x, W1);
    k_att1<<<(NN * 8 + 255) / 256, 256, 0, s1>>>(AS1, AD1);
    cudaEventRecord(evJoin, s1);

    // Main stream: CSR build.
    k_zero<<<(NN + 255) / 256, 256>>>();
    k_count<<<(EE / 4 + 255) / 256, 256>>>(edst4);
    k_scan1<<<nb, 1024>>>();
    k_scan2<<<1, 1024>>>(nb);
    k_scan3<<<nb, 1024>>>();
    k_fill<<<(EE / 4 + 255) / 256, 256>>>(esrc4, edst4);

    // Join: aggregation needs both CSR and h1/att1.
    cudaStreamWaitEvent(0, evJoin, 0);

    k_agg1<<<(NN * 32 + 255) / 256, 256>>>(B1);

    k_gemm2<<<NN / 32, 256>>>(W2);
    k_att2<<<(NN * 32 + 255) / 256, 256>>>(AS2, AD2);
    k_agg2<<<(NN * 32 + 255) / 256, 256>>>(B2, batch);

    k_mlp<<<GG, 128>>>(LW1, LB1, LW2, LB2, out);
}

// round 8
// speedup vs baseline: 1.0954x; 1.0326x over previous
#include <cuda_runtime.h>

#define NN 100000
#define EE 3200000
#define GG 512
#define INC 128

// ---------------- scratch (static device globals; no allocation) -------------
__device__ int   g_deg[NN];          // zeroed by k_scan3 each pass (starts 0)
__device__ int   g_rowptr[NN + 1];
__device__ int   g_cursor[NN];
__device__ int   g_bsums[1024];
__device__ int   g_boffs[1024];
__device__ int   g_col[EE];
__device__ float g_h1[NN * 64];
__device__ float g_as1[NN * 8];
__device__ float g_ad1[NN * 8];
__device__ float g_out1[NN * 64];
__device__ float g_h2[NN * 64];
__device__ float g_as2[NN];
__device__ float g_ad2[NN];
__device__ float g_pool[GG * 64];    // zeroed by k_mlp each pass (starts 0)
__device__ int   g_gcnt[GG];         // zeroed by k_mlp each pass (starts 0)

// ---------------- CSR build --------------------------------------------------
__global__ void k_count(const int4* __restrict__ dst4) {
    int i = blockIdx.x * blockDim.x + threadIdx.x;
    if (i < EE / 4) {
        int4 d = dst4[i];
        atomicAdd(&g_deg[d.x], 1);
        atomicAdd(&g_deg[d.y], 1);
        atomicAdd(&g_deg[d.z], 1);
        atomicAdd(&g_deg[d.w], 1);
    }
}

__global__ void k_scan1() {
    __shared__ int sh[1024];
    int t = threadIdx.x;
    int i = blockIdx.x * 1024 + t;
    int v = (i < NN) ? g_deg[i] : 0;
    sh[t] = v; __syncthreads();
    for (int off = 1; off < 1024; off <<= 1) {
        int tv = (t >= off) ? sh[t - off] : 0;
        __syncthreads();
        sh[t] += tv;
        __syncthreads();
    }
    if (i < NN) g_rowptr[i] = sh[t] - v;     // exclusive
    if (t == 1023) g_bsums[blockIdx.x] = sh[1023];
}

__global__ void k_scan2(int nb) {
    __shared__ int sh[1024];
    int t = threadIdx.x;
    int v = (t < nb) ? g_bsums[t] : 0;
    sh[t] = v; __syncthreads();
    for (int off = 1; off < 1024; off <<= 1) {
        int tv = (t >= off) ? sh[t - off] : 0;
        __syncthreads();
        sh[t] += tv;
        __syncthreads();
    }
    g_boffs[t] = sh[t] - v;
    if (t == 1023) g_rowptr[NN] = sh[1023];  // == EE
}

__global__ void k_scan3() {
    int i = blockIdx.x * 1024 + threadIdx.x;
    if (i < NN) {
        int v = g_rowptr[i] + g_boffs[blockIdx.x];
        g_rowptr[i] = v;
        g_cursor[i] = v;
        g_deg[i] = 0;                        // ready for next replay
    }
}

__global__ void k_fill(const int4* __restrict__ src4, const int4* __restrict__ dst4) {
    int i = blockIdx.x * blockDim.x + threadIdx.x;
    if (i < EE / 4) {
        int4 s = src4[i];
        int4 d = dst4[i];
        g_col[atomicAdd(&g_cursor[d.x], 1)] = s.x;
        g_col[atomicAdd(&g_cursor[d.y], 1)] = s.y;
        g_col[atomicAdd(&g_cursor[d.z], 1)] = s.z;
        g_col[atomicAdd(&g_cursor[d.w], 1)] = s.w;
    }
}

// ---------------- GEMM core (x[N,K] @ W[K,64]) -------------------------------
// 256 threads/block, 32 rows/block; thread t: rows gr,gr+1 cols cg..cg+3.
template <int K>
__device__ __forceinline__ void gemm_core(const float* __restrict__ x,
                                          const float* __restrict__ W,
                                          float* __restrict__ out,
                                          float4& a0, float4& a1,
                                          int& gr, int& cg) {
    __shared__ float ws[K * 64];
    __shared__ float xs[32 * K];
    int t = threadIdx.x;
    int row0 = blockIdx.x * 32;
    for (int i = t; i < K * 64; i += 256) ws[i] = W[i];
    for (int i = t; i < 32 * K; i += 256) {
        int r = i / K, c = i - r * K;
        xs[i] = x[(row0 + r) * K + c];     // NN % 32 == 0
    }
    __syncthreads();
    cg = (t & 15) * 4;
    int r0 = (t >> 4) * 2;
    a0 = make_float4(0.f, 0.f, 0.f, 0.f);
    a1 = make_float4(0.f, 0.f, 0.f, 0.f);
    #pragma unroll 8
    for (int k = 0; k < K; k++) {
        float4 w = *(const float4*)&ws[k * 64 + cg];
        float x0 = xs[r0 * K + k];
        float x1 = xs[(r0 + 1) * K + k];
        a0.x += x0 * w.x; a0.y += x0 * w.y; a0.z += x0 * w.z; a0.w += x0 * w.w;
        a1.x += x1 * w.x; a1.y += x1 * w.y; a1.z += x1 * w.z; a1.w += x1 * w.w;
    }
    gr = row0 + r0;
    *(float4*)&out[gr * 64 + cg] = a0;
    *(float4*)&out[(gr + 1) * 64 + cg] = a1;
}

#define DOT4(A, V) ((A).x * (V).x + (A).y * (V).y + (A).z * (V).z + (A).w * (V).w)

// gemm1 + att1 fused: per-head (8 cols) dots; each head's 8 cols live in a
// lane pair (t, t^1) -> one shfl_xor combine, even lane writes.
__global__ void k_gemm1(const float* __restrict__ x, const float* __restrict__ W,
                        const float* __restrict__ asrc, const float* __restrict__ adst) {
    float4 a0, a1; int gr, cg;
    gemm_core<128>(x, W, g_h1, a0, a1, gr, cg);
    float4 avs = *(const float4*)&asrc[cg];
    float4 avd = *(const float4*)&adst[cg];
    float s0 = DOT4(a0, avs), d0 = DOT4(a0, avd);
    float s1 = DOT4(a1, avs), d1 = DOT4(a1, avd);
    s0 += __shfl_xor_sync(0xffffffffu, s0, 1);
    d0 += __shfl_xor_sync(0xffffffffu, d0, 1);
    s1 += __shfl_xor_sync(0xffffffffu, s1, 1);
    d1 += __shfl_xor_sync(0xffffffffu, d1, 1);
    int t = threadIdx.x;
    if (!(t & 1)) {
        int head = (t & 15) >> 1;
        g_as1[gr * 8 + head] = s0;
        g_ad1[gr * 8 + head] = d0;
        g_as1[(gr + 1) * 8 + head] = s1;
        g_ad1[(gr + 1) * 8 + head] = d1;
    }
}

// gemm2 + att2 fused: full-row (64 cols) dot across the 16-lane group.
__global__ void k_gemm2(const float* __restrict__ W,
                        const float* __restrict__ asrc, const float* __restrict__ adst) {
    float4 a0, a1; int gr, cg;
    gemm_core<64>(g_out1, W, g_h2, a0, a1, gr, cg);
    float4 avs = *(const float4*)&asrc[cg];
    float4 avd = *(const float4*)&adst[cg];
    float s0 = DOT4(a0, avs), d0 = DOT4(a0, avd);
    float s1 = DOT4(a1, avs), d1 = DOT4(a1, avd);
    #pragma unroll
    for (int off = 1; off < 16; off <<= 1) {
        s0 += __shfl_xor_sync(0xffffffffu, s0, off);
        d0 += __shfl_xor_sync(0xffffffffu, d0, off);
        s1 += __shfl_xor_sync(0xffffffffu, s1, off);
        d1 += __shfl_xor_sync(0xffffffffu, d1, off);
    }
    if ((threadIdx.x & 15) == 0) {
        g_as2[gr] = s0; g_ad2[gr] = d0;
        g_as2[gr + 1] = s1; g_ad2[gr + 1] = d1;
    }
}

// ---------------- GAT aggregation (warp per dst node) ------------------------
#define LEAKY(v) ((v) > 0.f ? (v) : 0.2f * (v))

__global__ void __launch_bounds__(256) k_agg1(const float* __restrict__ b1) {
    int gt = blockIdx.x * blockDim.x + threadIdx.x;
    int node = gt >> 5;
    if (node >= NN) return;
    int lane = gt & 31;
    int head = lane >> 2;
    float adv = g_ad1[node * 8 + head];
    float e = g_as1[node * 8 + head] + adv;     // self loop
    float p = __expf(LEAKY(e));
    const float2* __restrict__ H = (const float2*)g_h1;
    float2 hv = __ldg(&H[node * 32 + lane]);
    float s = p, a0 = hv.x * p, a1 = hv.y * p;
    int i = g_rowptr[node], en = g_rowptr[node + 1];
    for (; i + 4 <= en; i += 4) {
        int s0 = g_col[i],     s1 = g_col[i + 1];
        int s2 = g_col[i + 2], s3 = g_col[i + 3];
        float e0 = __ldg(&g_as1[s0 * 8 + head]);
        float e1 = __ldg(&g_as1[s1 * 8 + head]);
        float e2 = __ldg(&g_as1[s2 * 8 + head]);
        float e3 = __ldg(&g_as1[s3 * 8 + head]);
        float2 x0 = __ldg(&H[s0 * 32 + lane]);
        float2 x1 = __ldg(&H[s1 * 32 + lane]);
        float2 x2 = __ldg(&H[s2 * 32 + lane]);
        float2 x3 = __ldg(&H[s3 * 32 + lane]);
        float p0 = __expf(LEAKY(e0 + adv));
        float p1 = __expf(LEAKY(e1 + adv));
        float p2 = __expf(LEAKY(e2 + adv));
        float p3 = __expf(LEAKY(e3 + adv));
        s  += (p0 + p1) + (p2 + p3);
        a0 += x0.x * p0 + x1.x * p1 + x2.x * p2 + x3.x * p3;
        a1 += x0.y * p0 + x1.y * p1 + x2.y * p2 + x3.y * p3;
    }
    for (; i < en; i++) {
        int src = g_col[i];
        float ev = __ldg(&g_as1[src * 8 + head]) + adv;
        float pp = __expf(LEAKY(ev));
        float2 xv = __ldg(&H[src * 32 + lane]);
        s += pp; a0 += xv.x * pp; a1 += xv.y * pp;
    }
    float inv = 1.f / fmaxf(s, 1e-16f);
    float v0 = a0 * inv + b1[lane * 2];
    float v1 = a1 * inv + b1[lane * 2 + 1];
    v0 = v0 > 0.f ? v0 : (__expf(v0) - 1.f);   // ELU
    v1 = v1 > 0.f ? v1 : (__expf(v1) - 1.f);
    ((float2*)(g_out1 + node * 64))[lane] = make_float2(v0, v1);
}

// agg2 + global_mean_pool (sum part) fused.
__global__ void __launch_bounds__(256) k_agg2(const float* __restrict__ b2,
                                              const int* __restrict__ batch) {
    int gt = blockIdx.x * blockDim.x + threadIdx.x;
    int node = gt >> 5;
    if (node >= NN) return;
    int lane = gt & 31;
    float adv = g_ad2[node];
    float e = g_as2[node] + adv;
    float p = __expf(LEAKY(e));
    const float2* __restrict__ H = (const float2*)g_h2;
    float2 hv = __ldg(&H[node * 32 + lane]);
    float s = p, a0 = hv.x * p, a1 = hv.y * p;
    int i = g_rowptr[node], en = g_rowptr[node + 1];
    for (; i + 4 <= en; i += 4) {
        int s0 = g_col[i],     s1 = g_col[i + 1];
        int s2 = g_col[i + 2], s3 = g_col[i + 3];
        float e0 = __ldg(&g_as2[s0]);
        float e1 = __ldg(&g_as2[s1]);
        float e2 = __ldg(&g_as2[s2]);
        float e3 = __ldg(&g_as2[s3]);
        float2 x0 = __ldg(&H[s0 * 32 + lane]);
        float2 x1 = __ldg(&H[s1 * 32 + lane]);
        float2 x2 = __ldg(&H[s2 * 32 + lane]);
        float2 x3 = __ldg(&H[s3 * 32 + lane]);
        float p0 = __expf(LEAKY(e0 + adv));
        float p1 = __expf(LEAKY(e1 + adv));
        float p2 = __expf(LEAKY(e2 + adv));
        float p3 = __expf(LEAKY(e3 + adv));
        s  += (p0 + p1) + (p2 + p3);
        a0 += x0.x * p0 + x1.x * p1 + x2.x * p2 + x3.x * p3;
        a1 += x0.y * p0 + x1.y * p1 + x2.y * p2 + x3.y * p3;
    }
    for (; i < en; i++) {
        int src = g_col[i];
        float ev = __ldg(&g_as2[src]) + adv;
        float pp = __expf(LEAKY(ev));
        float2 xv = __ldg(&H[src * 32 + lane]);
        s += pp; a0 += xv.x * pp; a1 += xv.y * pp;
    }
    float inv = 1.f / fmaxf(s, 1e-16f);
    float v0 = a0 * inv + b2[lane * 2];
    float v1 = a1 * inv + b2[lane * 2 + 1];
    int b = batch[node];
    atomicAdd(&g_pool[b * 64 + lane * 2], v0);       // RED (no return)
    atomicAdd(&g_pool[b * 64 + lane * 2 + 1], v1);
    if (lane == 0) atomicAdd(&g_gcnt[b], 1);
}

// ---------------- MLP head (zeroes pool/gcnt for the next replay) -------------
__global__ void k_mlp(const float* __restrict__ lw1, const float* __restrict__ lb1,
                      const float* __restrict__ lw2, const float* __restrict__ lb2,
                      float* __restrict__ out) {
    int g = blockIdx.x;
    int t = threadIdx.x;   // 128
    __shared__ float gm[64];
    __shared__ float red[128];
    if (t < 64) {
        float c = (float)max(g_gcnt[g], 1);
        gm[t] = g_pool[g * 64 + t] / c;
    }
    __syncthreads();
    // restore invariant for next graph replay
    if (t < 64) g_pool[g * 64 + t] = 0.f;
    if (t == 64) g_gcnt[g] = 0;
    float acc = lb1[t];
    #pragma unroll 8
    for (int k = 0; k < 64; k++) acc += gm[k] * lw1[k * 128 + t];
    float hv = acc > 0.f ? acc : (__expf(acc) - 1.f);   // ELU
    red[t] = hv * lw2[t];
    __syncthreads();
    for (int sft = 64; sft > 0; sft >>= 1) {
        if (t < sft) red[t] += red[t + sft];
        __syncthreads();
    }
    if (t == 0) out[g] = red[0] + lb2[0];
}

// ---------------- launch ------------------------------------------------------
extern "C" void kernel_launch(void* const* d_in, const int* in_sizes, int n_in,
                              void* d_out, int out_size) {
    int iEI, iBatch, iW1, iAS1, iAD1, iB1, iW2, iAS2, iAD2, iB2, iLW1, iLB1, iLW2, iLB2;
    if (in_sizes[1] == 2 * EE) {
        iEI = 1; iBatch = 2; iW1 = 3; iAS1 = 4; iAD1 = 5; iB1 = 6;
        iW2 = 7; iAS2 = 8; iAD2 = 9; iB2 = 10; iLW1 = 11; iLB1 = 12; iLW2 = 13; iLB2 = 14;
    } else {
        iW1 = 1; iAS1 = 2; iAD1 = 3; iB1 = 4; iW2 = 5; iAS2 = 6; iAD2 = 7; iB2 = 8;
        iLW1 = 9; iLB1 = 10; iLW2 = 11; iLB2 = 12; iEI = 13; iBatch = 14;
    }
    const float* x     = (const float*)d_in[0];
    const int*   ei    = (const int*)d_in[iEI];
    const int*   batch = (const int*)d_in[iBatch];
    const float* W1    = (const float*)d_in[iW1];
    const float* AS1   = (const float*)d_in[iAS1];
    const float* AD1   = (const float*)d_in[iAD1];
    const float* B1    = (const float*)d_in[iB1];
    const float* W2    = (const float*)d_in[iW2];
    const float* AS2   = (const float*)d_in[iAS2];
    const float* AD2   = (const float*)d_in[iAD2];
    const float* B2    = (const float*)d_in[iB2];
    const float* LW1   = (const float*)d_in[iLW1];
    const float* LB1   = (const float*)d_in[iLB1];
    const float* LW2   = (const float*)d_in[iLW2];
    const float* LB2   = (const float*)d_in[iLB2];
    float* out = (float*)d_out;

    const int4* esrc4 = (const int4*)ei;
    const int4* edst4 = (const int4*)(ei + EE);

    int nb = (NN + 1023) / 1024;

    static cudaStream_t s1 = nullptr;
    static cudaEvent_t evFork = nullptr, evJoin = nullptr;
    if (!s1) {
        cudaStreamCreateWithFlags(&s1, cudaStreamNonBlocking);
        cudaEventCreateWithFlags(&evFork, cudaEventDisableTiming);
        cudaEventCreateWithFlags(&evJoin, cudaEventDisableTiming);
    }

    // Fork: layer-1 GEMM(+att1 fused) concurrent with CSR build.
    cudaEventRecord(evFork, 0);
    cudaStreamWaitEvent(s1, evFork, 0);
    k_gemm1<<<NN / 32, 256, 0, s1>>>(x, W1, AS1, AD1);
    cudaEventRecord(evJoin, s1);

    // Main stream: CSR build.
    k_count<<<(EE / 4 + 255) / 256, 256>>>(edst4);
    k_scan1<<<nb, 1024>>>();
    k_scan2<<<1, 1024>>>(nb);
    k_scan3<<<nb, 1024>>>();
    k_fill<<<(EE / 4 + 255) / 256, 256>>>(esrc4, edst4);

    // Join: aggregation needs both CSR and h1/att1.
    cudaStreamWaitEvent(0, evJoin, 0);

    k_agg1<<<(NN * 32 + 255) / 256, 256>>>(B1);
    k_gemm2<<<NN / 32, 256>>>(W2, AS2, AD2);
    k_agg2<<<(NN * 32 + 255) / 256, 256>>>(B2, batch);
    k_mlp<<<GG, 128>>>(LW1, LB1, LW2, LB2, out);
}

// round 9
// speedup vs baseline: 1.1063x; 1.0100x over previous
#include <cuda_runtime.h>
#include <cuda_fp16.h>

#define NN 100000
#define EE 3200000
#define GG 512
#define INC 128

// ---------------- scratch (static device globals; no allocation) -------------
__device__ int    g_deg[NN];          // zeroed by k_scan3 each pass (starts 0)
__device__ int    g_rowptr[NN + 1];
__device__ int    g_cursor[NN];
__device__ int    g_bsums[1024];
__device__ int    g_boffs[1024];
__device__ int    g_col[EE];
__device__ __half g_h1h[NN * 64];     // fp16 h1 (gather payload)
__device__ float  g_as1[NN * 8];
__device__ float  g_ad1[NN * 8];
__device__ float  g_out1[NN * 64];
__device__ __half g_h2h[NN * 64];     // fp16 h2 (gather payload)
__device__ float  g_as2[NN];
__device__ float  g_ad2[NN];
__device__ float  g_pool[GG * 64];    // zeroed by k_mlp each pass (starts 0)
__device__ int    g_gcnt[GG];         // zeroed by k_mlp each pass (starts 0)

// ---------------- CSR build --------------------------------------------------
__global__ void k_count(const int4* __restrict__ dst4) {
    int i = blockIdx.x * blockDim.x + threadIdx.x;
    if (i < EE / 4) {
        int4 d = dst4[i];
        atomicAdd(&g_deg[d.x], 1);
        atomicAdd(&g_deg[d.y], 1);
        atomicAdd(&g_deg[d.z], 1);
        atomicAdd(&g_deg[d.w], 1);
    }
}

__global__ void k_scan1() {
    __shared__ int sh[1024];
    int t = threadIdx.x;
    int i = blockIdx.x * 1024 + t;
    int v = (i < NN) ? g_deg[i] : 0;
    sh[t] = v; __syncthreads();
    for (int off = 1; off < 1024; off <<= 1) {
        int tv = (t >= off) ? sh[t - off] : 0;
        __syncthreads();
        sh[t] += tv;
        __syncthreads();
    }
    if (i < NN) g_rowptr[i] = sh[t] - v;     // exclusive
    if (t == 1023) g_bsums[blockIdx.x] = sh[1023];
}

__global__ void k_scan2(int nb) {
    __shared__ int sh[1024];
    int t = threadIdx.x;
    int v = (t < nb) ? g_bsums[t] : 0;
    sh[t] = v; __syncthreads();
    for (int off = 1; off < 1024; off <<= 1) {
        int tv = (t >= off) ? sh[t - off] : 0;
        __syncthreads();
        sh[t] += tv;
        __syncthreads();
    }
    g_boffs[t] = sh[t] - v;
    if (t == 1023) g_rowptr[NN] = sh[1023];  // == EE
}

__global__ void k_scan3() {
    int i = blockIdx.x * 1024 + threadIdx.x;
    if (i < NN) {
        int v = g_rowptr[i] + g_boffs[blockIdx.x];
        g_rowptr[i] = v;
        g_cursor[i] = v;
        g_deg[i] = 0;                        // ready for next replay
    }
}

__global__ void k_fill(const int4* __restrict__ src4, const int4* __restrict__ dst4) {
    int i = blockIdx.x * blockDim.x + threadIdx.x;
    if (i < EE / 4) {
        int4 s = src4[i];
        int4 d = dst4[i];
        g_col[atomicAdd(&g_cursor[d.x], 1)] = s.x;
        g_col[atomicAdd(&g_cursor[d.y], 1)] = s.y;
        g_col[atomicAdd(&g_cursor[d.z], 1)] = s.z;
        g_col[atomicAdd(&g_cursor[d.w], 1)] = s.w;
    }
}

// ---------------- GEMM core (x[N,K] @ W[K,64]) -------------------------------
// 256 threads/block, 32 rows/block; thread t: rows gr,gr+1 cols cg..cg+3.
// No float output store; epilogues store fp16 + att scores from registers.
template <int K>
__device__ __forceinline__ void gemm_core(const float* __restrict__ x,
                                          const float* __restrict__ W,
                                          float4& a0, float4& a1,
                                          int& gr, int& cg) {
    __shared__ float ws[K * 64];
    __shared__ float xs[32 * K];
    int t = threadIdx.x;
    int row0 = blockIdx.x * 32;
    for (int i = t; i < K * 64; i += 256) ws[i] = W[i];
    for (int i = t; i < 32 * K; i += 256) {
        int r = i / K, c = i - r * K;
        xs[i] = x[(row0 + r) * K + c];     // NN % 32 == 0
    }
    __syncthreads();
    cg = (t & 15) * 4;
    int r0 = (t >> 4) * 2;
    a0 = make_float4(0.f, 0.f, 0.f, 0.f);
    a1 = make_float4(0.f, 0.f, 0.f, 0.f);
    #pragma unroll 8
    for (int k = 0; k < K; k++) {
        float4 w = *(const float4*)&ws[k * 64 + cg];
        float x0 = xs[r0 * K + k];
        float x1 = xs[(r0 + 1) * K + k];
        a0.x += x0 * w.x; a0.y += x0 * w.y; a0.z += x0 * w.z; a0.w += x0 * w.w;
        a1.x += x1 * w.x; a1.y += x1 * w.y; a1.z += x1 * w.z; a1.w += x1 * w.w;
    }
    gr = row0 + r0;
}

__device__ __forceinline__ void store_half4(__half* dst, float4 v) {
    union { __half2 h2[2]; uint2 u; } pk;
    pk.h2[0] = __floats2half2_rn(v.x, v.y);
    pk.h2[1] = __floats2half2_rn(v.z, v.w);
    *(uint2*)dst = pk.u;
}

#define DOT4(A, V) ((A).x * (V).x + (A).y * (V).y + (A).z * (V).z + (A).w * (V).w)

// gemm1 + att1 fused; h1 stored fp16 only.
__global__ void k_gemm1(const float* __restrict__ x, const float* __restrict__ W,
                        const float* __restrict__ asrc, const float* __restrict__ adst) {
    float4 a0, a1; int gr, cg;
    gemm_core<128>(x, W, a0, a1, gr, cg);
    store_half4(&g_h1h[gr * 64 + cg], a0);
    store_half4(&g_h1h[(gr + 1) * 64 + cg], a1);
    float4 avs = *(const float4*)&asrc[cg];
    float4 avd = *(const float4*)&adst[cg];
    float s0 = DOT4(a0, avs), d0 = DOT4(a0, avd);
    float s1 = DOT4(a1, avs), d1 = DOT4(a1, avd);
    s0 += __shfl_xor_sync(0xffffffffu, s0, 1);
    d0 += __shfl_xor_sync(0xffffffffu, d0, 1);
    s1 += __shfl_xor_sync(0xffffffffu, s1, 1);
    d1 += __shfl_xor_sync(0xffffffffu, d1, 1);
    int t = threadIdx.x;
    if (!(t & 1)) {
        int head = (t & 15) >> 1;
        g_as1[gr * 8 + head] = s0;
        g_ad1[gr * 8 + head] = d0;
        g_as1[(gr + 1) * 8 + head] = s1;
        g_ad1[(gr + 1) * 8 + head] = d1;
    }
}

// gemm2 + att2 fused; h2 stored fp16 only.
__global__ void k_gemm2(const float* __restrict__ W,
                        const float* __restrict__ asrc, const float* __restrict__ adst) {
    float4 a0, a1; int gr, cg;
    gemm_core<64>(g_out1, W, a0, a1, gr, cg);
    store_half4(&g_h2h[gr * 64 + cg], a0);
    store_half4(&g_h2h[(gr + 1) * 64 + cg], a1);
    float4 avs = *(const float4*)&asrc[cg];
    float4 avd = *(const float4*)&adst[cg];
    float s0 = DOT4(a0, avs), d0 = DOT4(a0, avd);
    float s1 = DOT4(a1, avs), d1 = DOT4(a1, avd);
    #pragma unroll
    for (int off = 1; off < 16; off <<= 1) {
        s0 += __shfl_xor_sync(0xffffffffu, s0, off);
        d0 += __shfl_xor_sync(0xffffffffu, d0, off);
        s1 += __shfl_xor_sync(0xffffffffu, s1, off);
        d1 += __shfl_xor_sync(0xffffffffu, d1, off);
    }
    if ((threadIdx.x & 15) == 0) {
        g_as2[gr] = s0; g_ad2[gr] = d0;
        g_as2[gr + 1] = s1; g_ad2[gr + 1] = d1;
    }
}

// ---------------- GAT aggregation (warp per dst node) ------------------------
#define LEAKY(v) ((v) > 0.f ? (v) : 0.2f * (v))

__global__ void __launch_bounds__(256) k_agg1(const float* __restrict__ b1) {
    int gt = blockIdx.x * blockDim.x + threadIdx.x;
    int node = gt >> 5;
    if (node >= NN) return;
    int lane = gt & 31;
    int head = lane >> 2;
    float adv = g_ad1[node * 8 + head];
    float e = g_as1[node * 8 + head] + adv;     // self loop
    float p = __expf(LEAKY(e));
    const __half2* __restrict__ H = (const __half2*)g_h1h;
    float2 hv = __half22float2(__ldg(&H[node * 32 + lane]));
    float s = p, a0 = hv.x * p, a1 = hv.y * p;
    int i = g_rowptr[node], en = g_rowptr[node + 1];
    for (; i + 4 <= en; i += 4) {
        int s0 = g_col[i],     s1 = g_col[i + 1];
        int s2 = g_col[i + 2], s3 = g_col[i + 3];
        float e0 = __ldg(&g_as1[s0 * 8 + head]);
        float e1 = __ldg(&g_as1[s1 * 8 + head]);
        float e2 = __ldg(&g_as1[s2 * 8 + head]);
        float e3 = __ldg(&g_as1[s3 * 8 + head]);
        float2 x0 = __half22float2(__ldg(&H[s0 * 32 + lane]));
        float2 x1 = __half22float2(__ldg(&H[s1 * 32 + lane]));
        float2 x2 = __half22float2(__ldg(&H[s2 * 32 + lane]));
        float2 x3 = __half22float2(__ldg(&H[s3 * 32 + lane]));
        float p0 = __expf(LEAKY(e0 + adv));
        float p1 = __expf(LEAKY(e1 + adv));
        float p2 = __expf(LEAKY(e2 + adv));
        float p3 = __expf(LEAKY(e3 + adv));
        s  += (p0 + p1) + (p2 + p3);
        a0 += x0.x * p0 + x1.x * p1 + x2.x * p2 + x3.x * p3;
        a1 += x0.y * p0 + x1.y * p1 + x2.y * p2 + x3.y * p3;
    }
    for (; i < en; i++) {
        int src = g_col[i];
        float ev = __ldg(&g_as1[src * 8 + head]) + adv;
        float pp = __expf(LEAKY(ev));
        float2 xv = __half22float2(__ldg(&H[src * 32 + lane]));
        s += pp; a0 += xv.x * pp; a1 += xv.y * pp;
    }
    float inv = 1.f / fmaxf(s, 1e-16f);
    float v0 = a0 * inv + b1[lane * 2];
    float v1 = a1 * inv + b1[lane * 2 + 1];
    v0 = v0 > 0.f ? v0 : (__expf(v0) - 1.f);   // ELU
    v1 = v1 > 0.f ? v1 : (__expf(v1) - 1.f);
    ((float2*)(g_out1 + node * 64))[lane] = make_float2(v0, v1);
}

// agg2 + global_mean_pool (sum part) fused.
__global__ void __launch_bounds__(256) k_agg2(const float* __restrict__ b2,
                                              const int* __restrict__ batch) {
    int gt = blockIdx.x * blockDim.x + threadIdx.x;
    int node = gt >> 5;
    if (node >= NN) return;
    int lane = gt & 31;
    float adv = g_ad2[node];
    float e = g_as2[node] + adv;
    float p = __expf(LEAKY(e));
    const __half2* __restrict__ H = (const __half2*)g_h2h;
    float2 hv = __half22float2(__ldg(&H[node * 32 + lane]));
    float s = p, a0 = hv.x * p, a1 = hv.y * p;
    int i = g_rowptr[node], en = g_rowptr[node + 1];
    for (; i + 4 <= en; i += 4) {
        int s0 = g_col[i],     s1 = g_col[i + 1];
        int s2 = g_col[i + 2], s3 = g_col[i + 3];
        float e0 = __ldg(&g_as2[s0]);
        float e1 = __ldg(&g_as2[s1]);
        float e2 = __ldg(&g_as2[s2]);
        float e3 = __ldg(&g_as2[s3]);
        float2 x0 = __half22float2(__ldg(&H[s0 * 32 + lane]));
        float2 x1 = __half22float2(__ldg(&H[s1 * 32 + lane]));
        float2 x2 = __half22float2(__ldg(&H[s2 * 32 + lane]));
        float2 x3 = __half22float2(__ldg(&H[s3 * 32 + lane]));
        float p0 = __expf(LEAKY(e0 + adv));
        float p1 = __expf(LEAKY(e1 + adv));
        float p2 = __expf(LEAKY(e2 + adv));
        float p3 = __expf(LEAKY(e3 + adv));
        s  += (p0 + p1) + (p2 + p3);
        a0 += x0.x * p0 + x1.x * p1 + x2.x * p2 + x3.x * p3;
        a1 += x0.y * p0 + x1.y * p1 + x2.y * p2 + x3.y * p3;
    }
    for (; i < en; i++) {
        int src = g_col[i];
        float ev = __ldg(&g_as2[src]) + adv;
        float pp = __expf(LEAKY(ev));
        float2 xv = __half22float2(__ldg(&H[src * 32 + lane]));
        s += pp; a0 += xv.x * pp; a1 += xv.y * pp;
    }
    float inv = 1.f / fmaxf(s, 1e-16f);
    float v0 = a0 * inv + b2[lane * 2];
    float v1 = a1 * inv + b2[lane * 2 + 1];
    int b = batch[node];
    atomicAdd(&g_pool[b * 64 + lane * 2], v0);       // RED (no return)
    atomicAdd(&g_pool[b * 64 + lane * 2 + 1], v1);
    if (lane == 0) atomicAdd(&g_gcnt[b], 1);
}

// ---------------- MLP head (zeroes pool/gcnt for the next replay) -------------
__global__ void k_mlp(const float* __restrict__ lw1, const float* __restrict__ lb1,
                      const float* __restrict__ lw2, const float* __restrict__ lb2,
                      float* __restrict__ out) {
    int g = blockIdx.x;
    int t = threadIdx.x;   // 128
    __shared__ float gm[64];
    __shared__ float red[128];
    if (t < 64) {
        float c = (float)max(g_gcnt[g], 1);
        gm[t] = g_pool[g * 64 + t] / c;
    }
    __syncthreads();
    if (t < 64) g_pool[g * 64 + t] = 0.f;
    if (t == 64) g_gcnt[g] = 0;
    float acc = lb1[t];
    #pragma unroll 8
    for (int k = 0; k < 64; k++) acc += gm[k] * lw1[k * 128 + t];
    float hv = acc > 0.f ? acc : (__expf(acc) - 1.f);   // ELU
    red[t] = hv * lw2[t];
    __syncthreads();
    for (int sft = 64; sft > 0; sft >>= 1) {
        if (t < sft) red[t] += red[t + sft];
        __syncthreads();
    }
    if (t == 0) out[g] = red[0] + lb2[0];
}

// ---------------- launch ------------------------------------------------------
extern "C" void kernel_launch(void* const* d_in, const int* in_sizes, int n_in,
                              void* d_out, int out_size) {
    int iEI, iBatch, iW1, iAS1, iAD1, iB1, iW2, iAS2, iAD2, iB2, iLW1, iLB1, iLW2, iLB2;
    if (in_sizes[1] == 2 * EE) {
        iEI = 1; iBatch = 2; iW1 = 3; iAS1 = 4; iAD1 = 5; iB1 = 6;
        iW2 = 7; iAS2 = 8; iAD2 = 9; iB2 = 10; iLW1 = 11; iLB1 = 12; iLW2 = 13; iLB2 = 14;
    } else {
        iW1 = 1; iAS1 = 2; iAD1 = 3; iB1 = 4; iW2 = 5; iAS2 = 6; iAD2 = 7; iB2 = 8;
        iLW1 = 9; iLB1 = 10; iLW2 = 11; iLB2 = 12; iEI = 13; iBatch = 14;
    }
    const float* x     = (const float*)d_in[0];
    const int*   ei    = (const int*)d_in[iEI];
    const int*   batch = (const int*)d_in[iBatch];
    const float* W1    = (const float*)d_in[iW1];
    const float* AS1   = (const float*)d_in[iAS1];
    const float* AD1   = (const float*)d_in[iAD1];
    const float* B1    = (const float*)d_in[iB1];
    const float* W2    = (const float*)d_in[iW2];
    const float* AS2   = (const float*)d_in[iAS2];
    const float* AD2   = (const float*)d_in[iAD2];
    const float* B2    = (const float*)d_in[iB2];
    const float* LW1   = (const float*)d_in[iLW1];
    const float* LB1   = (const float*)d_in[iLB1];
    const float* LW2   = (const float*)d_in[iLW2];
    const float* LB2   = (const float*)d_in[iLB2];
    float* out = (float*)d_out;

    const int4* esrc4 = (const int4*)ei;
    const int4* edst4 = (const int4*)(ei + EE);

    int nb = (NN + 1023) / 1024;

    static cudaStream_t s1 = nullptr;
    static cudaEvent_t evFork = nullptr, evJoin = nullptr;
    if (!s1) {
        cudaStreamCreateWithFlags(&s1, cudaStreamNonBlocking);
        cudaEventCreateWithFlags(&evFork, cudaEventDisableTiming);
        cudaEventCreateWithFlags(&evJoin, cudaEventDisableTiming);
    }

    // Fork: layer-1 GEMM(+att1 fused) concurrent with CSR build.
    cudaEventRecord(evFork, 0);
    cudaStreamWaitEvent(s1, evFork, 0);
    k_gemm1<<<NN / 32, 256, 0, s1>>>(x, W1, AS1, AD1);
    cudaEventRecord(evJoin, s1);

    // Main stream: CSR build.
    k_count<<<(EE / 4 + 255) / 256, 256>>>(edst4);
    k_scan1<<<nb, 1024>>>();
    k_scan2<<<1, 1024>>>(nb);
    k_scan3<<<nb, 1024>>>();
    k_fill<<<(EE / 4 + 255) / 256, 256>>>(esrc4, edst4);

    // Join: aggregation needs both CSR and h1/att1.
    cudaStreamWaitEvent(0, evJoin, 0);

    k_agg1<<<(NN * 32 + 255) / 256, 256>>>(B1);
    k_gemm2<<<NN / 32, 256>>>(W2, AS2, AD2);
    k_agg2<<<(NN * 32 + 255) / 256, 256>>>(B2, batch);
    k_mlp<<<GG, 128>>>(LW1, LB1, LW2, LB2, out);
}